// round 6
// baseline (speedup 1.0000x reference)
#include <cuda_runtime.h>
#include <math.h>

#define NB 16
#define NS 2048
#define NIN 128

typedef unsigned long long u64;
typedef unsigned int u32;

__device__ __forceinline__ u64 f2fma(u64 a, u64 b, u64 c) {
    u64 d; asm("fma.rn.f32x2 %0,%1,%2,%3;" : "=l"(d) : "l"(a), "l"(b), "l"(c)); return d;
}
__device__ __forceinline__ u64 f2add(u64 a, u64 b) {
    u64 d; asm("add.rn.f32x2 %0,%1,%2;" : "=l"(d) : "l"(a), "l"(b)); return d;
}
__device__ __forceinline__ u64 pk2(float x, float y) {
    u64 d; asm("mov.b64 %0,{%1,%2};" : "=l"(d) : "f"(x), "f"(y)); return d;
}
__device__ __forceinline__ float2 unpk(u64 v) {
    float2 r; asm("mov.b64 {%0,%1},%2;" : "=f"(r.x), "=f"(r.y) : "l"(v)); return r;
}
__device__ __forceinline__ void unpku(u64 v, u32& lo, u32& hi) {
    asm("mov.b64 {%0,%1},%2;" : "=r"(lo), "=r"(hi) : "l"(v));
}

// Scratch
__device__ float g_h0[NB * NS];
__device__ float g_h1[NB * NS];
__device__ float g_h2[NB * NS];
__device__ float g_cs[NB * NS];          // 0.5*|h|^2
__device__ ulonglong2 g_pp0[NB * NS / 2]; // row pairs: {(-h0_e,-h0_o),(-h1_e,-h1_o)}
__device__ ulonglong2 g_pp1[NB * NS / 2]; // row pairs: {(-h2_e,-h2_o),(cs_e, cs_o)}
__device__ int g_cidx[NB * NS];
__device__ int g_cn[NB];
__device__ int g_maxbits[NB];
__device__ unsigned int g_total[NB];
__device__ unsigned int g_det[NB];
__device__ unsigned int g_vert[NB];

// h = relu(x@w1+b1)@w2+b2 ; writes scalars + negated row-pair arrays.
__global__ __launch_bounds__(128) void k_embed(
    const float* __restrict__ x, const float* __restrict__ w1,
    const float* __restrict__ b1, const float* __restrict__ w2,
    const float* __restrict__ b2)
{
    if (blockIdx.x == 0 && threadIdx.x < NB) {
        g_maxbits[threadIdx.x] = 0;
        g_total[threadIdx.x] = 0u;
        g_det[threadIdx.x] = 0u;
        g_vert[threadIdx.x] = 0u;
    }

    __shared__ float s_w1[NIN * 6];
    __shared__ float s_w2[18];
    __shared__ float s_b1[6];
    __shared__ float s_b2[3];
    for (int i = threadIdx.x; i < NIN * 6; i += blockDim.x) s_w1[i] = w1[i];
    if (threadIdx.x < 18) s_w2[threadIdx.x] = w2[threadIdx.x];
    if (threadIdx.x < 6)  s_b1[threadIdx.x] = b1[threadIdx.x];
    if (threadIdx.x < 3)  s_b2[threadIdx.x] = b2[threadIdx.x];
    __syncthreads();

    int row = blockIdx.x * blockDim.x + threadIdx.x;
    if (row >= NB * NS) return;

    const float4* xr = (const float4*)(x + (size_t)row * NIN);
    float acc[6];
#pragma unroll
    for (int e = 0; e < 6; e++) acc[e] = s_b1[e];

#pragma unroll 16
    for (int q = 0; q < NIN / 4; q++) {
        float4 v = xr[q];
#pragma unroll
        for (int e = 0; e < 6; e++) {
            acc[e] = fmaf(v.x, s_w1[(4 * q + 0) * 6 + e], acc[e]);
            acc[e] = fmaf(v.y, s_w1[(4 * q + 1) * 6 + e], acc[e]);
            acc[e] = fmaf(v.z, s_w1[(4 * q + 2) * 6 + e], acc[e]);
            acc[e] = fmaf(v.w, s_w1[(4 * q + 3) * 6 + e], acc[e]);
        }
    }
#pragma unroll
    for (int e = 0; e < 6; e++) acc[e] = fmaxf(acc[e], 0.0f);

    float h0 = s_b2[0], h1 = s_b2[1], h2 = s_b2[2];
#pragma unroll
    for (int e = 0; e < 6; e++) {
        h0 = fmaf(acc[e], s_w2[e * 3 + 0], h0);
        h1 = fmaf(acc[e], s_w2[e * 3 + 1], h1);
        h2 = fmaf(acc[e], s_w2[e * 3 + 2], h2);
    }
    float cs = 0.5f * (h0 * h0 + h1 * h1 + h2 * h2);
    g_h0[row] = h0;
    g_h1[row] = h1;
    g_h2[row] = h2;
    g_cs[row] = cs;

    // pack row pairs (even, odd) via shfl
    float h0n = __shfl_down_sync(0xffffffffu, h0, 1);
    float h1n = __shfl_down_sync(0xffffffffu, h1, 1);
    float h2n = __shfl_down_sync(0xffffffffu, h2, 1);
    float csn = __shfl_down_sync(0xffffffffu, cs, 1);
    if ((threadIdx.x & 1) == 0) {
        ulonglong2 a; a.x = pk2(-h0, -h0n); a.y = pk2(-h1, -h1n);
        ulonglong2 b; b.x = pk2(-h2, -h2n); b.y = pk2(cs, csn);
        g_pp0[row >> 1] = a;
        g_pp1[row >> 1] = b;
    }
}

// One block per batch: centroid, radii, shell lower bound d_lb, candidate set C2.
// Exactness: d(s,t) <= r_s + r_t, so any point with r < sqrt(d_lb) - rmax cannot
// be an endpoint of a pair beating d_lb. max = max(d_lb, max over C2 x C2).
__global__ __launch_bounds__(256) void k_cand() {
    int b = blockIdx.x;
    int tid = threadIdx.x;
    const int base = b * NS;

    __shared__ float s_r2[NS];
    __shared__ float red[256];
    __shared__ int s_idx[NS];
    __shared__ int s_cnt;
    __shared__ float s_mu0, s_mu1, s_mu2, s_r2max, s_dlb;

    // mean
    float a0 = 0, a1 = 0, a2 = 0;
    for (int i = tid; i < NS; i += 256) {
        a0 += g_h0[base + i]; a1 += g_h1[base + i]; a2 += g_h2[base + i];
    }
    red[tid] = a0; __syncthreads();
    for (int o = 128; o > 0; o >>= 1) { if (tid < o) red[tid] += red[tid + o]; __syncthreads(); }
    if (tid == 0) s_mu0 = red[0] * (1.0f / NS); __syncthreads();
    red[tid] = a1; __syncthreads();
    for (int o = 128; o > 0; o >>= 1) { if (tid < o) red[tid] += red[tid + o]; __syncthreads(); }
    if (tid == 0) s_mu1 = red[0] * (1.0f / NS); __syncthreads();
    red[tid] = a2; __syncthreads();
    for (int o = 128; o > 0; o >>= 1) { if (tid < o) red[tid] += red[tid + o]; __syncthreads(); }
    if (tid == 0) s_mu2 = red[0] * (1.0f / NS); __syncthreads();

    float mu0 = s_mu0, mu1 = s_mu1, mu2 = s_mu2;
    float mx = 0.0f;
    for (int i = tid; i < NS; i += 256) {
        float d0 = g_h0[base + i] - mu0;
        float d1 = g_h1[base + i] - mu1;
        float d2 = g_h2[base + i] - mu2;
        float r2 = d0 * d0 + d1 * d1 + d2 * d2;
        s_r2[i] = r2;
        mx = fmaxf(mx, r2);
    }
    red[tid] = mx; __syncthreads();
    for (int o = 128; o > 0; o >>= 1) { if (tid < o) red[tid] = fmaxf(red[tid], red[tid + o]); __syncthreads(); }
    if (tid == 0) { s_r2max = red[0]; s_cnt = 0; }
    __syncthreads();

    // C1: r >= 0.8 rmax  <=>  r2 >= 0.64 r2max
    float thr1 = 0.64f * s_r2max;
    for (int i = tid; i < NS; i += 256) {
        if (s_r2[i] >= thr1) {
            int k = atomicAdd(&s_cnt, 1);
            s_idx[k] = i;
        }
    }
    __syncthreads();
    int n1 = s_cnt;

    // d_lb: exact d2 over C1 pairs
    float dlb = 0.0f;
    for (int p = tid; p < n1 * n1; p += 256) {
        int i = s_idx[p / n1], j = s_idx[p % n1];
        float dot = fmaf(g_h0[base + i], g_h0[base + j],
                    fmaf(g_h1[base + i], g_h1[base + j],
                         g_h2[base + i] * g_h2[base + j]));
        dlb = fmaxf(dlb, 2.0f * (g_cs[base + i] + g_cs[base + j] - dot));
    }
    red[tid] = dlb; __syncthreads();
    for (int o = 128; o > 0; o >>= 1) { if (tid < o) red[tid] = fmaxf(red[tid], red[tid + o]); __syncthreads(); }
    if (tid == 0) {
        s_dlb = red[0];
        g_maxbits[b] = __float_as_int(fmaxf(red[0], 0.0f));
        s_cnt = 0;
    }
    __syncthreads();

    // C2: r >= sqrt(d_lb) - rmax
    float tau = sqrtf(fmaxf(s_dlb, 0.0f)) - sqrtf(s_r2max);
    float thr2 = (tau > 0.0f) ? tau * tau : -1.0f;
    for (int i = tid; i < NS; i += 256) {
        if (s_r2[i] >= thr2) {
            int k = atomicAdd(&s_cnt, 1);
            g_cidx[base + k] = i;
        }
    }
    __syncthreads();
    if (tid == 0) g_cn[b] = s_cnt;
}

// Exact max over candidate pairs. grid (8, NB).
__global__ __launch_bounds__(256) void k_maxexact() {
    int b = blockIdx.y;
    const int base = b * NS;
    int n = g_cn[b];
    float m = 0.0f;
    for (int i = blockIdx.x; i < n; i += 8) {
        int ii = g_cidx[base + i];
        float h0 = g_h0[base + ii], h1 = g_h1[base + ii], h2 = g_h2[base + ii];
        float cs = g_cs[base + ii];
        for (int j = threadIdx.x; j < n; j += 256) {
            int jj = g_cidx[base + j];
            float dot = fmaf(h0, g_h0[base + jj],
                        fmaf(h1, g_h1[base + jj], h2 * g_h2[base + jj]));
            m = fmaxf(m, 2.0f * (cs + g_cs[base + jj] - dot));
        }
    }
    __shared__ float red[256];
    red[threadIdx.x] = m;
    __syncthreads();
    for (int o = 128; o > 0; o >>= 1) {
        if (threadIdx.x < o) red[threadIdx.x] = fmaxf(red[threadIdx.x], red[threadIdx.x + o]);
        __syncthreads();
    }
    if (threadIdx.x == 0) atomicMax(&g_maxbits[b], __float_as_int(red[0]));
}

// Super-diagonal band sum (offsets 1..9). grid (8, NB).
__global__ __launch_bounds__(256) void k_det(const float* __restrict__ thp) {
    int b = blockIdx.y;
    int tid = threadIdx.x;
    int s = blockIdx.x * 256 + tid;
    const int base = b * NS;
    float th = *thp;
    float sig = 1.0f / (1.0f + expf(-th));
    float halfthr2 = 0.5f * sig * sig * __int_as_float(g_maxbits[b]);

    unsigned int sum = 0;
    float h0 = g_h0[base + s], h1 = g_h1[base + s], h2 = g_h2[base + s];
    float cs = g_cs[base + s];
#pragma unroll
    for (int o = 1; o <= 9; o++) {
        int t = s + o;
        if (t < NS) {
            float dot = fmaf(h0, g_h0[base + t],
                        fmaf(h1, g_h1[base + t], h2 * g_h2[base + t]));
            sum += (dot > (cs + g_cs[base + t] - halfthr2)) ? 1u : 0u;
        }
    }
    __shared__ unsigned int red[256];
    red[tid] = sum;
    __syncthreads();
    for (int o = 128; o > 0; o >>= 1) {
        if (tid < o) red[tid] += red[tid + o];
        __syncthreads();
    }
    if (tid == 0) atomicAdd(&g_det[b], red[0]);
}

// Pass 2: total + vertical run-starts.
// Rows packed in f32x2 lanes (2 rows/op); 4 cols/thread; bits interleaved
// 2 cols per 32-bit word (16 rows); run detection via 2-bit-shift popc.
// 64 rows x 1024 cols per block. grid: x = cb + 2*rc, y = batch.
__global__ __launch_bounds__(256, 4) void k_stats(const float* __restrict__ thp) {
    int xx = blockIdx.x;
    int cb = xx & 1;
    int rc = xx >> 1;
    int b = blockIdx.y;
    int r0 = rc * 64;
    int tid = threadIdx.x;
    const int base = b * NS;
    const int pbase = (b * NS + r0) >> 1;

    __shared__ ulonglong2 sP0[32], sP1[32];
    if (tid < 32) {
        sP0[tid] = g_pp0[pbase + tid];
        sP1[tid] = g_pp1[pbase + tid];
    }

    float th = *thp;
    float sig = 1.0f / (1.0f + expf(-th));
    float hth = 0.5f * sig * sig * __int_as_float(g_maxbits[b]);

    // 4 columns per thread: cA..cD, duplicated constants
    int cA = cb * 1024 + tid;
    float tA0s = g_h0[base + cA],        tB0s = g_h0[base + cA + 256];
    float tC0s = g_h0[base + cA + 512],  tD0s = g_h0[base + cA + 768];
    float tA1s = g_h1[base + cA],        tB1s = g_h1[base + cA + 256];
    float tC1s = g_h1[base + cA + 512],  tD1s = g_h1[base + cA + 768];
    float tA2s = g_h2[base + cA],        tB2s = g_h2[base + cA + 256];
    float tC2s = g_h2[base + cA + 512],  tD2s = g_h2[base + cA + 768];
    float dAs = g_cs[base + cA] - hth,       dBs = g_cs[base + cA + 256] - hth;
    float dCs = g_cs[base + cA + 512] - hth, dDs = g_cs[base + cA + 768] - hth;

    u64 tA0 = pk2(tA0s, tA0s), tA1 = pk2(tA1s, tA1s), tA2 = pk2(tA2s, tA2s), dA = pk2(dAs, dAs);
    u64 tB0 = pk2(tB0s, tB0s), tB1 = pk2(tB1s, tB1s), tB2 = pk2(tB2s, tB2s), dB = pk2(dBs, dBs);
    u64 tC0 = pk2(tC0s, tC0s), tC1 = pk2(tC1s, tC1s), tC2 = pk2(tC2s, tC2s), dC = pk2(dCs, dCs);
    u64 tD0 = pk2(tD0s, tD0s), tD1 = pk2(tD1s, tD1s), tD2 = pk2(tD2s, tD2s), dD = pk2(dDs, dDs);

    // scalar R-bit of (row r, col c): R <=> cs_r + (cs_c - hth) - dot < 0 sign trick
#define SCBIT(rh0, rh1, rh2, rcs, t0s, t1s, t2s, ds)                              \
    (__float_as_uint(fmaf(-(rh0), (t0s), fmaf(-(rh1), (t1s),                      \
        fmaf(-(rh2), (t2s), (rcs) + (ds))))) >> 31)

    // prologue row r0-1 and epilogue row r0+64 (scalar, from global broadcast)
    u32 pcAB = 0, pcCD = 0;
    if (r0 > 0) {
        int r = base + r0 - 1;
        float rh0 = g_h0[r], rh1 = g_h1[r], rh2 = g_h2[r], rcs = g_cs[r];
        u32 aA = SCBIT(rh0, rh1, rh2, rcs, tA0s, tA1s, tA2s, dAs);
        u32 aB = SCBIT(rh0, rh1, rh2, rcs, tB0s, tB1s, tB2s, dBs);
        u32 aC = SCBIT(rh0, rh1, rh2, rcs, tC0s, tC1s, tC2s, dCs);
        u32 aD = SCBIT(rh0, rh1, rh2, rcs, tD0s, tD1s, tD2s, dDs);
        pcAB = (aA << 1) | aB;
        pcCD = (aC << 1) | aD;
    }
    u32 neAB = 0, neCD = 0;
    if (r0 + 64 < NS) {
        int r = base + r0 + 64;
        float rh0 = g_h0[r], rh1 = g_h1[r], rh2 = g_h2[r], rcs = g_cs[r];
        u32 aA = SCBIT(rh0, rh1, rh2, rcs, tA0s, tA1s, tA2s, dAs);
        u32 aB = SCBIT(rh0, rh1, rh2, rcs, tB0s, tB1s, tB2s, dBs);
        u32 aC = SCBIT(rh0, rh1, rh2, rcs, tC0s, tC1s, tC2s, dCs);
        u32 aD = SCBIT(rh0, rh1, rh2, rcs, tD0s, tD1s, tD2s, dDs);
        neAB = (aA << 1) | aB;
        neCD = (aC << 1) | aD;
    }
    __syncthreads();

    u32 utot = 0, uvert = 0;
    u32 pendAB = 0, pendCD = 0;

#define PROCESS2(pd, pc, nf)                                                     \
    {                                                                            \
        u32 prevw = (pd >> 2) | (pc << 30);                                      \
        u32 nextw = (pd << 2) | (nf);                                            \
        uvert += __popc(pd & ~prevw & nextw);                                    \
        utot += __popc(pd);                                                      \
        pc = pd & 3u;                                                            \
    }

#pragma unroll
    for (int g = 0; g < 4; g++) {
        u32 wAB = 0, wCD = 0;
#pragma unroll
        for (int jj = 0; jj < 8; jj++) {
            int j = g * 8 + jj;
            ulonglong2 P0 = sP0[j];
            ulonglong2 P1 = sP1[j];
            u64 qA = f2fma(P0.x, tA0, f2fma(P0.y, tA1, f2fma(P1.x, tA2, f2add(P1.y, dA))));
            u64 qB = f2fma(P0.x, tB0, f2fma(P0.y, tB1, f2fma(P1.x, tB2, f2add(P1.y, dB))));
            u64 qC = f2fma(P0.x, tC0, f2fma(P0.y, tC1, f2fma(P1.x, tC2, f2add(P1.y, dC))));
            u64 qD = f2fma(P0.x, tD0, f2fma(P0.y, tD1, f2fma(P1.x, tD2, f2add(P1.y, dD))));
            u32 lA, hA, lB, hB, lC, hC, lD, hD;
            unpku(qA, lA, hA); unpku(qB, lB, hB);
            unpku(qC, lC, hC); unpku(qD, lD, hD);
            // even row then odd row; per row: col X then col Y
            wAB = __funnelshift_l(lA, wAB, 1);
            wAB = __funnelshift_l(lB, wAB, 1);
            wAB = __funnelshift_l(hA, wAB, 1);
            wAB = __funnelshift_l(hB, wAB, 1);
            wCD = __funnelshift_l(lC, wCD, 1);
            wCD = __funnelshift_l(lD, wCD, 1);
            wCD = __funnelshift_l(hC, wCD, 1);
            wCD = __funnelshift_l(hD, wCD, 1);
        }
        if (g > 0) {
            u32 nfAB = (wAB >> 30) & 3u;
            u32 nfCD = (wCD >> 30) & 3u;
            PROCESS2(pendAB, pcAB, nfAB);
            PROCESS2(pendCD, pcCD, nfCD);
        }
        pendAB = wAB;
        pendCD = wCD;
    }
    PROCESS2(pendAB, pcAB, neAB);
    PROCESS2(pendCD, pcCD, neCD);

#undef PROCESS2
#undef SCBIT

    __shared__ unsigned int rt[256], rv[256];
    rt[tid] = utot;
    rv[tid] = uvert;
    __syncthreads();
    for (int o = 128; o > 0; o >>= 1) {
        if (tid < o) { rt[tid] += rt[tid + o]; rv[tid] += rv[tid + o]; }
        __syncthreads();
    }
    if (tid == 0) {
        atomicAdd(&g_total[b], rt[0]);
        atomicAdd(&g_vert[b], rv[0]);
    }
}

// Final: metrics [B,4] @ w3 [4,64] + b3 -> relu
__global__ __launch_bounds__(256) void k_final(
    const float* __restrict__ w3, const float* __restrict__ b3,
    float* __restrict__ out)
{
    int tid = blockIdx.x * blockDim.x + threadIdx.x;
    if (tid >= NB * 64) return;
    int b = tid >> 6;
    int j = tid & 63;

    float total = (float)g_total[b];
    float denom = total + 1e-6f;
    float rr = total * (1.0f / ((float)NS * (float)NS));
    float det = (float)g_det[b] / denom;
    float lam = (float)g_vert[b] / denom;
    float entr = -total * logf(1.0f + 1e-6f);

    float v = fmaf(rr, w3[j],
              fmaf(det, w3[64 + j],
              fmaf(lam, w3[128 + j],
              fmaf(entr, w3[192 + j], b3[j]))));
    out[tid] = fmaxf(v, 0.0f);
}

extern "C" void kernel_launch(void* const* d_in, const int* in_sizes, int n_in,
                              void* d_out, int out_size) {
    const float* x  = (const float*)d_in[0];
    const float* th = (const float*)d_in[1];
    const float* w1 = (const float*)d_in[2];
    const float* b1 = (const float*)d_in[3];
    const float* w2 = (const float*)d_in[4];
    const float* b2 = (const float*)d_in[5];
    const float* w3 = (const float*)d_in[6];
    const float* b3 = (const float*)d_in[7];
    float* out = (float*)d_out;

    k_embed<<<(NB * NS + 127) / 128, 128>>>(x, w1, b1, w2, b2);
    k_cand<<<NB, 256>>>();
    k_maxexact<<<dim3(8, NB), 256>>>();
    k_det<<<dim3(8, NB), 256>>>(th);
    k_stats<<<dim3(64, NB), 256>>>(th);
    k_final<<<(NB * 64 + 255) / 256, 256>>>(w3, b3, out);
}

// round 7
// speedup vs baseline: 4.3012x; 4.3012x over previous
#include <cuda_runtime.h>
#include <math.h>

#define NB 16
#define NS 2048
#define NIN 128

typedef unsigned long long u64;
typedef unsigned int u32;

__device__ __forceinline__ u64 f2fma(u64 a, u64 b, u64 c) {
    u64 d; asm("fma.rn.f32x2 %0,%1,%2,%3;" : "=l"(d) : "l"(a), "l"(b), "l"(c)); return d;
}
__device__ __forceinline__ u64 f2add(u64 a, u64 b) {
    u64 d; asm("add.rn.f32x2 %0,%1,%2;" : "=l"(d) : "l"(a), "l"(b)); return d;
}
__device__ __forceinline__ u64 pk2(float x, float y) {
    u64 d; asm("mov.b64 %0,{%1,%2};" : "=l"(d) : "f"(x), "f"(y)); return d;
}
__device__ __forceinline__ float2 unpk(u64 v) {
    float2 r; asm("mov.b64 {%0,%1},%2;" : "=f"(r.x), "=f"(r.y) : "l"(v)); return r;
}
__device__ __forceinline__ void unpku(u64 v, u32& lo, u32& hi) {
    asm("mov.b64 {%0,%1},%2;" : "=r"(lo), "=r"(hi) : "l"(v));
}

// Scratch
__device__ float g_h0[NB * NS];
__device__ float g_h1[NB * NS];
__device__ float g_h2[NB * NS];
__device__ float g_cs[NB * NS];           // 0.5*|h|^2
__device__ ulonglong2 g_pp0[NB * NS / 2]; // row pairs: {(-h0_e,-h0_o),(-h1_e,-h1_o)}
__device__ ulonglong2 g_pp1[NB * NS / 2]; // row pairs: {(-h2_e,-h2_o),(cs_e, cs_o)}
__device__ int g_maxbits[NB];
__device__ unsigned int g_total[NB];
__device__ unsigned int g_det[NB];
__device__ unsigned int g_vert[NB];

// h = relu(x@w1+b1)@w2+b2 ; writes scalars + negated row-pair arrays.
__global__ __launch_bounds__(128) void k_embed(
    const float* __restrict__ x, const float* __restrict__ w1,
    const float* __restrict__ b1, const float* __restrict__ w2,
    const float* __restrict__ b2)
{
    if (blockIdx.x == 0 && threadIdx.x < NB) {
        g_maxbits[threadIdx.x] = 0;
        g_total[threadIdx.x] = 0u;
        g_det[threadIdx.x] = 0u;
        g_vert[threadIdx.x] = 0u;
    }

    __shared__ float s_w1[NIN * 6];
    __shared__ float s_w2[18];
    __shared__ float s_b1[6];
    __shared__ float s_b2[3];
    for (int i = threadIdx.x; i < NIN * 6; i += blockDim.x) s_w1[i] = w1[i];
    if (threadIdx.x < 18) s_w2[threadIdx.x] = w2[threadIdx.x];
    if (threadIdx.x < 6)  s_b1[threadIdx.x] = b1[threadIdx.x];
    if (threadIdx.x < 3)  s_b2[threadIdx.x] = b2[threadIdx.x];
    __syncthreads();

    int row = blockIdx.x * blockDim.x + threadIdx.x;
    if (row >= NB * NS) return;

    const float4* xr = (const float4*)(x + (size_t)row * NIN);
    float acc[6];
#pragma unroll
    for (int e = 0; e < 6; e++) acc[e] = s_b1[e];

#pragma unroll 16
    for (int q = 0; q < NIN / 4; q++) {
        float4 v = xr[q];
#pragma unroll
        for (int e = 0; e < 6; e++) {
            acc[e] = fmaf(v.x, s_w1[(4 * q + 0) * 6 + e], acc[e]);
            acc[e] = fmaf(v.y, s_w1[(4 * q + 1) * 6 + e], acc[e]);
            acc[e] = fmaf(v.z, s_w1[(4 * q + 2) * 6 + e], acc[e]);
            acc[e] = fmaf(v.w, s_w1[(4 * q + 3) * 6 + e], acc[e]);
        }
    }
#pragma unroll
    for (int e = 0; e < 6; e++) acc[e] = fmaxf(acc[e], 0.0f);

    float h0 = s_b2[0], h1 = s_b2[1], h2 = s_b2[2];
#pragma unroll
    for (int e = 0; e < 6; e++) {
        h0 = fmaf(acc[e], s_w2[e * 3 + 0], h0);
        h1 = fmaf(acc[e], s_w2[e * 3 + 1], h1);
        h2 = fmaf(acc[e], s_w2[e * 3 + 2], h2);
    }
    float cs = 0.5f * (h0 * h0 + h1 * h1 + h2 * h2);
    g_h0[row] = h0;
    g_h1[row] = h1;
    g_h2[row] = h2;
    g_cs[row] = cs;

    float h0n = __shfl_down_sync(0xffffffffu, h0, 1);
    float h1n = __shfl_down_sync(0xffffffffu, h1, 1);
    float h2n = __shfl_down_sync(0xffffffffu, h2, 1);
    float csn = __shfl_down_sync(0xffffffffu, cs, 1);
    if ((threadIdx.x & 1) == 0) {
        ulonglong2 a; a.x = pk2(-h0, -h0n); a.y = pk2(-h1, -h1n);
        ulonglong2 b; b.x = pk2(-h2, -h2n); b.y = pk2(cs, csn);
        g_pp0[row >> 1] = a;
        g_pp1[row >> 1] = b;
    }
}

// Pass 1: per-batch max of q = cs_r + cs_c - dot = d2/2, brute force,
// row-pair packed. 64-row x 1024-col tiles, triangle cover (48 tiles/batch).
// grid.x = 48: xx<32 -> (rc=xx, cb=1); else (rc=xx-32, cb=0, rc<16).
__global__ __launch_bounds__(256, 4) void k_max() {
    int b = blockIdx.y;
    int xx = blockIdx.x;
    int rc, cb;
    if (xx < 32) { rc = xx; cb = 1; } else { rc = xx - 32; cb = 0; }
    int r0 = rc * 64;
    int tid = threadIdx.x;
    const int base = b * NS;
    const int pbase = (b * NS + r0) >> 1;

    __shared__ ulonglong2 sP0[32], sP1[32];
    if (tid < 32) {
        sP0[tid] = g_pp0[pbase + tid];
        sP1[tid] = g_pp1[pbase + tid];
    }
    __syncthreads();

    int cA = cb * 1024 + tid;
    float tA0s = g_h0[base + cA],        tB0s = g_h0[base + cA + 256];
    float tC0s = g_h0[base + cA + 512],  tD0s = g_h0[base + cA + 768];
    float tA1s = g_h1[base + cA],        tB1s = g_h1[base + cA + 256];
    float tC1s = g_h1[base + cA + 512],  tD1s = g_h1[base + cA + 768];
    float tA2s = g_h2[base + cA],        tB2s = g_h2[base + cA + 256];
    float tC2s = g_h2[base + cA + 512],  tD2s = g_h2[base + cA + 768];
    float dAs = g_cs[base + cA],         dBs = g_cs[base + cA + 256];
    float dCs = g_cs[base + cA + 512],   dDs = g_cs[base + cA + 768];

    u64 tA0 = pk2(tA0s, tA0s), tA1 = pk2(tA1s, tA1s), tA2 = pk2(tA2s, tA2s), dA = pk2(dAs, dAs);
    u64 tB0 = pk2(tB0s, tB0s), tB1 = pk2(tB1s, tB1s), tB2 = pk2(tB2s, tB2s), dB = pk2(dBs, dBs);
    u64 tC0 = pk2(tC0s, tC0s), tC1 = pk2(tC1s, tC1s), tC2 = pk2(tC2s, tC2s), dC = pk2(dCs, dCs);
    u64 tD0 = pk2(tD0s, tD0s), tD1 = pk2(tD1s, tD1s), tD2 = pk2(tD2s, tD2s), dD = pk2(dDs, dDs);

    float mA = 0.0f, mB = 0.0f, mC = 0.0f, mD = 0.0f;
#pragma unroll 8
    for (int j = 0; j < 32; j++) {
        ulonglong2 P0 = sP0[j];
        ulonglong2 P1 = sP1[j];
        u64 qA = f2fma(P0.x, tA0, f2fma(P0.y, tA1, f2fma(P1.x, tA2, f2add(P1.y, dA))));
        u64 qB = f2fma(P0.x, tB0, f2fma(P0.y, tB1, f2fma(P1.x, tB2, f2add(P1.y, dB))));
        u64 qC = f2fma(P0.x, tC0, f2fma(P0.y, tC1, f2fma(P1.x, tC2, f2add(P1.y, dC))));
        u64 qD = f2fma(P0.x, tD0, f2fma(P0.y, tD1, f2fma(P1.x, tD2, f2add(P1.y, dD))));
        float2 fA = unpk(qA), fB = unpk(qB), fC = unpk(qC), fD = unpk(qD);
        mA = fmaxf(mA, fmaxf(fA.x, fA.y));
        mB = fmaxf(mB, fmaxf(fB.x, fB.y));
        mC = fmaxf(mC, fmaxf(fC.x, fC.y));
        mD = fmaxf(mD, fmaxf(fD.x, fD.y));
    }
    float m = fmaxf(fmaxf(mA, mB), fmaxf(mC, mD));

    __shared__ float red[256];
    red[tid] = m;
    __syncthreads();
    for (int o = 128; o > 0; o >>= 1) {
        if (tid < o) red[tid] = fmaxf(red[tid], red[tid + o]);
        __syncthreads();
    }
    if (tid == 0) atomicMax(&g_maxbits[b], __float_as_int(2.0f * red[0]));
}

// Super-diagonal band sum (offsets 1..9), shared-tiled. grid (8, NB).
__global__ __launch_bounds__(256) void k_det(const float* __restrict__ thp) {
    int b = blockIdx.y;
    int tid = threadIdx.x;
    int s0 = blockIdx.x * 256;
    const int base = b * NS;
    float th = *thp;
    float sig = 1.0f / (1.0f + expf(-th));
    float halfthr2 = 0.5f * sig * sig * __int_as_float(g_maxbits[b]);

    __shared__ float sh0[272], sh1[272], sh2[272], shc[272];
    int nrows = (s0 + 265 <= NS) ? 265 : (NS - s0);
    for (int i = tid; i < nrows; i += 256) {
        sh0[i] = g_h0[base + s0 + i];
        sh1[i] = g_h1[base + s0 + i];
        sh2[i] = g_h2[base + s0 + i];
        shc[i] = g_cs[base + s0 + i];
    }
    __syncthreads();

    unsigned int sum = 0;
    float h0 = sh0[tid], h1 = sh1[tid], h2 = sh2[tid];
    float cs = sh0[tid] * 0.0f + shc[tid] - halfthr2;  // cs - halfthr2
#pragma unroll
    for (int o = 1; o <= 9; o++) {
        int t = tid + o;
        if (s0 + t < NS) {
            float dot = fmaf(h0, sh0[t], fmaf(h1, sh1[t], h2 * sh2[t]));
            sum += (dot > (cs + shc[t])) ? 1u : 0u;
        }
    }
    __shared__ unsigned int red[256];
    red[tid] = sum;
    __syncthreads();
    for (int o = 128; o > 0; o >>= 1) {
        if (tid < o) red[tid] += red[tid + o];
        __syncthreads();
    }
    if (tid == 0) atomicAdd(&g_det[b], red[0]);
}

// Pass 2: total + vertical run-starts. Rows packed in f32x2 lanes; 4 cols/thread;
// bits interleaved 2 cols per word. 64 rows x 1024 cols/block. grid (64, NB).
__global__ __launch_bounds__(256, 4) void k_stats(const float* __restrict__ thp) {
    int xx = blockIdx.x;
    int cb = xx & 1;
    int rc = xx >> 1;
    int b = blockIdx.y;
    int r0 = rc * 64;
    int tid = threadIdx.x;
    const int base = b * NS;
    const int pbase = (b * NS + r0) >> 1;

    __shared__ ulonglong2 sP0[32], sP1[32];
    if (tid < 32) {
        sP0[tid] = g_pp0[pbase + tid];
        sP1[tid] = g_pp1[pbase + tid];
    }

    float th = *thp;
    float sig = 1.0f / (1.0f + expf(-th));
    float hth = 0.5f * sig * sig * __int_as_float(g_maxbits[b]);

    int cA = cb * 1024 + tid;
    float tA0s = g_h0[base + cA],        tB0s = g_h0[base + cA + 256];
    float tC0s = g_h0[base + cA + 512],  tD0s = g_h0[base + cA + 768];
    float tA1s = g_h1[base + cA],        tB1s = g_h1[base + cA + 256];
    float tC1s = g_h1[base + cA + 512],  tD1s = g_h1[base + cA + 768];
    float tA2s = g_h2[base + cA],        tB2s = g_h2[base + cA + 256];
    float tC2s = g_h2[base + cA + 512],  tD2s = g_h2[base + cA + 768];
    float dAs = g_cs[base + cA] - hth,       dBs = g_cs[base + cA + 256] - hth;
    float dCs = g_cs[base + cA + 512] - hth, dDs = g_cs[base + cA + 768] - hth;

    u64 tA0 = pk2(tA0s, tA0s), tA1 = pk2(tA1s, tA1s), tA2 = pk2(tA2s, tA2s), dA = pk2(dAs, dAs);
    u64 tB0 = pk2(tB0s, tB0s), tB1 = pk2(tB1s, tB1s), tB2 = pk2(tB2s, tB2s), dB = pk2(dBs, dBs);
    u64 tC0 = pk2(tC0s, tC0s), tC1 = pk2(tC1s, tC1s), tC2 = pk2(tC2s, tC2s), dC = pk2(dCs, dCs);
    u64 tD0 = pk2(tD0s, tD0s), tD1 = pk2(tD1s, tD1s), tD2 = pk2(tD2s, tD2s), dD = pk2(dDs, dDs);

#define SCBIT(rh0, rh1, rh2, rcs, t0s, t1s, t2s, ds)                              \
    (__float_as_uint(fmaf(-(rh0), (t0s), fmaf(-(rh1), (t1s),                      \
        fmaf(-(rh2), (t2s), (rcs) + (ds))))) >> 31)

    u32 pcAB = 0, pcCD = 0;
    if (r0 > 0) {
        int r = base + r0 - 1;
        float rh0 = g_h0[r], rh1 = g_h1[r], rh2 = g_h2[r], rcs = g_cs[r];
        u32 aA = SCBIT(rh0, rh1, rh2, rcs, tA0s, tA1s, tA2s, dAs);
        u32 aB = SCBIT(rh0, rh1, rh2, rcs, tB0s, tB1s, tB2s, dBs);
        u32 aC = SCBIT(rh0, rh1, rh2, rcs, tC0s, tC1s, tC2s, dCs);
        u32 aD = SCBIT(rh0, rh1, rh2, rcs, tD0s, tD1s, tD2s, dDs);
        pcAB = (aA << 1) | aB;
        pcCD = (aC << 1) | aD;
    }
    u32 neAB = 0, neCD = 0;
    if (r0 + 64 < NS) {
        int r = base + r0 + 64;
        float rh0 = g_h0[r], rh1 = g_h1[r], rh2 = g_h2[r], rcs = g_cs[r];
        u32 aA = SCBIT(rh0, rh1, rh2, rcs, tA0s, tA1s, tA2s, dAs);
        u32 aB = SCBIT(rh0, rh1, rh2, rcs, tB0s, tB1s, tB2s, dBs);
        u32 aC = SCBIT(rh0, rh1, rh2, rcs, tC0s, tC1s, tC2s, dCs);
        u32 aD = SCBIT(rh0, rh1, rh2, rcs, tD0s, tD1s, tD2s, dDs);
        neAB = (aA << 1) | aB;
        neCD = (aC << 1) | aD;
    }
    __syncthreads();

    u32 utot = 0, uvert = 0;
    u32 pendAB = 0, pendCD = 0;

#define PROCESS2(pd, pc, nf)                                                     \
    {                                                                            \
        u32 prevw = (pd >> 2) | (pc << 30);                                      \
        u32 nextw = (pd << 2) | (nf);                                            \
        uvert += __popc(pd & ~prevw & nextw);                                    \
        utot += __popc(pd);                                                      \
        pc = pd & 3u;                                                            \
    }

#pragma unroll
    for (int g = 0; g < 4; g++) {
        u32 wAB = 0, wCD = 0;
#pragma unroll
        for (int jj = 0; jj < 8; jj++) {
            int j = g * 8 + jj;
            ulonglong2 P0 = sP0[j];
            ulonglong2 P1 = sP1[j];
            u64 qA = f2fma(P0.x, tA0, f2fma(P0.y, tA1, f2fma(P1.x, tA2, f2add(P1.y, dA))));
            u64 qB = f2fma(P0.x, tB0, f2fma(P0.y, tB1, f2fma(P1.x, tB2, f2add(P1.y, dB))));
            u64 qC = f2fma(P0.x, tC0, f2fma(P0.y, tC1, f2fma(P1.x, tC2, f2add(P1.y, dC))));
            u64 qD = f2fma(P0.x, tD0, f2fma(P0.y, tD1, f2fma(P1.x, tD2, f2add(P1.y, dD))));
            u32 lA, hA, lB, hB, lC, hC, lD, hD;
            unpku(qA, lA, hA); unpku(qB, lB, hB);
            unpku(qC, lC, hC); unpku(qD, lD, hD);
            wAB = __funnelshift_l(lA, wAB, 1);
            wAB = __funnelshift_l(lB, wAB, 1);
            wAB = __funnelshift_l(hA, wAB, 1);
            wAB = __funnelshift_l(hB, wAB, 1);
            wCD = __funnelshift_l(lC, wCD, 1);
            wCD = __funnelshift_l(lD, wCD, 1);
            wCD = __funnelshift_l(hC, wCD, 1);
            wCD = __funnelshift_l(hD, wCD, 1);
        }
        if (g > 0) {
            u32 nfAB = (wAB >> 30) & 3u;
            u32 nfCD = (wCD >> 30) & 3u;
            PROCESS2(pendAB, pcAB, nfAB);
            PROCESS2(pendCD, pcCD, nfCD);
        }
        pendAB = wAB;
        pendCD = wCD;
    }
    PROCESS2(pendAB, pcAB, neAB);
    PROCESS2(pendCD, pcCD, neCD);

#undef PROCESS2
#undef SCBIT

    __shared__ unsigned int rt[256], rv[256];
    rt[tid] = utot;
    rv[tid] = uvert;
    __syncthreads();
    for (int o = 128; o > 0; o >>= 1) {
        if (tid < o) { rt[tid] += rt[tid + o]; rv[tid] += rv[tid + o]; }
        __syncthreads();
    }
    if (tid == 0) {
        atomicAdd(&g_total[b], rt[0]);
        atomicAdd(&g_vert[b], rv[0]);
    }
}

// Final: metrics [B,4] @ w3 [4,64] + b3 -> relu
__global__ __launch_bounds__(256) void k_final(
    const float* __restrict__ w3, const float* __restrict__ b3,
    float* __restrict__ out)
{
    int tid = blockIdx.x * blockDim.x + threadIdx.x;
    if (tid >= NB * 64) return;
    int b = tid >> 6;
    int j = tid & 63;

    float total = (float)g_total[b];
    float denom = total + 1e-6f;
    float rr = total * (1.0f / ((float)NS * (float)NS));
    float det = (float)g_det[b] / denom;
    float lam = (float)g_vert[b] / denom;
    float entr = -total * logf(1.0f + 1e-6f);

    float v = fmaf(rr, w3[j],
              fmaf(det, w3[64 + j],
              fmaf(lam, w3[128 + j],
              fmaf(entr, w3[192 + j], b3[j]))));
    out[tid] = fmaxf(v, 0.0f);
}

extern "C" void kernel_launch(void* const* d_in, const int* in_sizes, int n_in,
                              void* d_out, int out_size) {
    const float* x  = (const float*)d_in[0];
    const float* th = (const float*)d_in[1];
    const float* w1 = (const float*)d_in[2];
    const float* b1 = (const float*)d_in[3];
    const float* w2 = (const float*)d_in[4];
    const float* b2 = (const float*)d_in[5];
    const float* w3 = (const float*)d_in[6];
    const float* b3 = (const float*)d_in[7];
    float* out = (float*)d_out;

    k_embed<<<(NB * NS + 127) / 128, 128>>>(x, w1, b1, w2, b2);
    k_max<<<dim3(48, NB), 256>>>();
    k_det<<<dim3(8, NB), 256>>>(th);
    k_stats<<<dim3(64, NB), 256>>>(th);
    k_final<<<(NB * 64 + 255) / 256, 256>>>(w3, b3, out);
}